// round 2
// baseline (speedup 1.0000x reference)
#include <cuda_runtime.h>

// L1Distance: out[i][j] = sum_d |x1[i,d] - x2[j,d]|   (mean-adjustment cancels,
// clamp_min(0) is a no-op on a sum of abs values).
// N1 = N2 = 2048, D = 64, fp32.
//
// Packed f32x2 formulation: B is negated at staging, A is stored duplicated
// {a,a} in smem so packed broadcasts load directly. Per 2 output pairs:
//   1x add.rn.f32x2 (diff, fma pipe) + 2x LOP3 (abs, alu pipe) + 1x add.rn.f32x2 (acc).
// => 1 fma-pipe instr per pair (vs 2 scalar FADD), abs work moved to alu pipe.

constexpr int D      = 64;
constexpr int TILE   = 128;   // 128x128 output tile per 256-thread block
constexpr int DCHUNK = 16;    // d staged in four chunks
constexpr int SA     = 260;   // As2 row stride in floats (256 data + 4 pad)
constexpr int SB     = 132;   // Bs  row stride in floats (128 data + 4 pad)

__device__ __forceinline__ unsigned long long addf32x2(unsigned long long a,
                                                       unsigned long long b) {
    unsigned long long d;
    asm("add.rn.f32x2 %0, %1, %2;" : "=l"(d) : "l"(a), "l"(b));
    return d;
}

__global__ __launch_bounds__(256, 2)
void l1dist_kernel(const float* __restrict__ x1, const float* __restrict__ x2,
                   float* __restrict__ out, int N2) {
    // As2[d][2*row+{0,1}] = x1[i0+row][dc+d]  (duplicated -> packed broadcast)
    // Bs [d][row]         = -x2[j0+row][dc+d] (negated   -> diff via packed add)
    __shared__ __align__(16) float As2[DCHUNK * SA];
    __shared__ __align__(16) float Bs[DCHUNK * SB];

    const int i0  = blockIdx.y * TILE;
    const int j0  = blockIdx.x * TILE;
    const int tid = (int)threadIdx.x;
    const int ty  = tid >> 4;   // 0..15
    const int tx  = tid & 15;   // 0..15

    unsigned long long acc[8][4];
#pragma unroll
    for (int m = 0; m < 8; m++)
#pragma unroll
        for (int np = 0; np < 4; np++) acc[m][np] = 0ULL;

    for (int dc = 0; dc < D; dc += DCHUNK) {
        // ---- stage chunk: 128 rows x 16 d per matrix = 512 float4, 2/thread ----
#pragma unroll
        for (int k = 0; k < 2; k++) {
            int idx = tid + k * 256;        // 0..511
            int row = idx >> 2;             // 0..127
            int d4  = (idx & 3) << 2;       // 0,4,8,12
            float4 a = *(const float4*)(x1 + (size_t)(i0 + row) * D + dc + d4);
            *(float2*)&As2[(d4 + 0) * SA + 2 * row] = make_float2(a.x, a.x);
            *(float2*)&As2[(d4 + 1) * SA + 2 * row] = make_float2(a.y, a.y);
            *(float2*)&As2[(d4 + 2) * SA + 2 * row] = make_float2(a.z, a.z);
            *(float2*)&As2[(d4 + 3) * SA + 2 * row] = make_float2(a.w, a.w);
            float4 b = *(const float4*)(x2 + (size_t)(j0 + row) * D + dc + d4);
            Bs[(d4 + 0) * SB + row] = -b.x;
            Bs[(d4 + 1) * SB + row] = -b.y;
            Bs[(d4 + 2) * SB + row] = -b.z;
            Bs[(d4 + 3) * SB + row] = -b.w;
        }
        __syncthreads();

#pragma unroll 4
        for (int d = 0; d < DCHUNK; d++) {
            const float* ar = &As2[d * SA];
            const float* br = &Bs[d * SB];
            // packed broadcasts {a_m, a_m} for m = ty*4+0..3 and 64+ty*4+0..3
            float4 a01 = *(const float4*)(ar + 8 * ty);
            float4 a23 = *(const float4*)(ar + 8 * ty + 4);
            float4 a45 = *(const float4*)(ar + 128 + 8 * ty);
            float4 a67 = *(const float4*)(ar + 128 + 8 * ty + 4);
            // packed negated b pairs for cols tx*4+0..3 and 64+tx*4+0..3
            float4 b03 = *(const float4*)(br + 4 * tx);
            float4 b47 = *(const float4*)(br + 64 + 4 * tx);

            unsigned long long ra[8], rb[4];
            ra[0] = ((const unsigned long long*)&a01)[0];
            ra[1] = ((const unsigned long long*)&a01)[1];
            ra[2] = ((const unsigned long long*)&a23)[0];
            ra[3] = ((const unsigned long long*)&a23)[1];
            ra[4] = ((const unsigned long long*)&a45)[0];
            ra[5] = ((const unsigned long long*)&a45)[1];
            ra[6] = ((const unsigned long long*)&a67)[0];
            ra[7] = ((const unsigned long long*)&a67)[1];
            rb[0] = ((const unsigned long long*)&b03)[0];
            rb[1] = ((const unsigned long long*)&b03)[1];
            rb[2] = ((const unsigned long long*)&b47)[0];
            rb[3] = ((const unsigned long long*)&b47)[1];

#pragma unroll
            for (int m = 0; m < 8; m++) {
#pragma unroll
                for (int np = 0; np < 4; np++) {
                    unsigned long long t = addf32x2(ra[m], rb[np]);  // a + (-b)
                    t &= 0x7fffffff7fffffffULL;                      // packed |.| (alu)
                    acc[m][np] = addf32x2(acc[m][np], t);
                }
            }
        }
        __syncthreads();
    }

    // ---- store: acc[m][0..1] -> cols tx*4+0..3, acc[m][2..3] -> cols 64+tx*4+0..3
#pragma unroll
    for (int m = 0; m < 8; m++) {
        int r = i0 + ty * 4 + (m & 3) + ((m >> 2) << 6);
        float* orow = out + (size_t)r * N2 + j0 + tx * 4;
        *(ulonglong2*)orow        = make_ulonglong2(acc[m][0], acc[m][1]);
        *(ulonglong2*)(orow + 64) = make_ulonglong2(acc[m][2], acc[m][3]);
    }
}

extern "C" void kernel_launch(void* const* d_in, const int* in_sizes, int n_in,
                              void* d_out, int out_size) {
    const float* x1 = (const float*)d_in[0];
    const float* x2 = (const float*)d_in[1];
    float* out = (float*)d_out;

    int N1 = in_sizes[0] / D;   // 2048
    int N2 = in_sizes[1] / D;   // 2048

    dim3 grid(N2 / TILE, N1 / TILE);   // 16 x 16 = 256 blocks
    l1dist_kernel<<<grid, 256>>>(x1, x2, out, N2);
}

// round 3
// speedup vs baseline: 1.0027x; 1.0027x over previous
#include <cuda_runtime.h>

// L1Distance via the min identity:
//   |a-b| = a + b - 2*min(a,b)
//   out[i][j] = rowsumA[i] + rowsumB[j] - 2 * sum_d min(x1[i,d], x2[j,d])
// The mean adjustment cancels exactly; clamp_min(0) applied in epilogue.
// Pairwise inner op = 1 FMNMX (alu pipe) + 1 FADD (fma pipe) per element-pair,
// halving the fma-pipe load vs the direct 2-FADD formulation.

constexpr int D      = 64;
constexpr int TILE   = 128;   // 128x128 output tile per 256-thread block
constexpr int DCHUNK = 32;    // d staged in two chunks
constexpr int STRIDE = 132;   // padded smem row stride (floats)

__device__ float d_rsA[2048];
__device__ float d_rsB[2048];

__global__ void rowsum_kernel(const float* __restrict__ x1,
                              const float* __restrict__ x2, int N) {
    int r = blockIdx.x * blockDim.x + threadIdx.x;
    if (r >= N) return;
    const float4* pa = (const float4*)(x1 + (size_t)r * D);
    const float4* pb = (const float4*)(x2 + (size_t)r * D);
    float sa = 0.f, sb = 0.f;
#pragma unroll
    for (int k = 0; k < D / 4; k++) {
        float4 va = pa[k];
        sa += (va.x + va.y) + (va.z + va.w);
        float4 vb = pb[k];
        sb += (vb.x + vb.y) + (vb.z + vb.w);
    }
    d_rsA[r] = sa;
    d_rsB[r] = sb;
}

__global__ __launch_bounds__(256, 2)
void l1dist_kernel(const float* __restrict__ x1, const float* __restrict__ x2,
                   float* __restrict__ out, int N2) {
    __shared__ __align__(16) float As[DCHUNK * STRIDE];  // As[d][row] = x1[i0+row][dc+d]
    __shared__ __align__(16) float Bs[DCHUNK * STRIDE];  // Bs[d][row] = x2[j0+row][dc+d]
    __shared__ float rsAs[TILE];
    __shared__ float rsBs[TILE];

    const int i0  = blockIdx.y * TILE;
    const int j0  = blockIdx.x * TILE;
    const int tid = (int)threadIdx.x;
    const int ty  = tid >> 4;   // 0..15
    const int tx  = tid & 15;   // 0..15

    // stage rowsums for this tile (synced by the first __syncthreads below)
    if (tid < 128) rsAs[tid] = d_rsA[i0 + tid];
    else           rsBs[tid - 128] = d_rsB[j0 + tid - 128];

    float acc[8][8];
#pragma unroll
    for (int m = 0; m < 8; m++)
#pragma unroll
        for (int n = 0; n < 8; n++) acc[m][n] = 0.0f;

    for (int dc = 0; dc < D; dc += DCHUNK) {
        // ---- stage chunk: 128 rows x 32 d per matrix, transposed into smem ----
#pragma unroll
        for (int k = 0; k < 4; k++) {
            int idx = tid + k * 256;        // 0..1023
            int row = idx >> 3;             // 0..127
            int d4  = (idx & 7) << 2;       // 0,4,...,28
            float4 a = *(const float4*)(x1 + (size_t)(i0 + row) * D + dc + d4);
            As[(d4 + 0) * STRIDE + row] = a.x;
            As[(d4 + 1) * STRIDE + row] = a.y;
            As[(d4 + 2) * STRIDE + row] = a.z;
            As[(d4 + 3) * STRIDE + row] = a.w;
            float4 b = *(const float4*)(x2 + (size_t)(j0 + row) * D + dc + d4);
            Bs[(d4 + 0) * STRIDE + row] = b.x;
            Bs[(d4 + 1) * STRIDE + row] = b.y;
            Bs[(d4 + 2) * STRIDE + row] = b.z;
            Bs[(d4 + 3) * STRIDE + row] = b.w;
        }
        __syncthreads();

        // ---- compute: acc[m][n] += min(a_m, b_n); 1 FMNMX(alu) + 1 FADD(fma) ----
#pragma unroll 4
        for (int d = 0; d < DCHUNK; d++) {
            const float* as = &As[d * STRIDE];
            const float* bs = &Bs[d * STRIDE];
            float4 a0 = *(const float4*)(as + ty * 4);
            float4 a1 = *(const float4*)(as + ty * 4 + 64);
            float4 b0 = *(const float4*)(bs + tx * 4);
            float4 b1 = *(const float4*)(bs + tx * 4 + 64);
            float ra[8] = {a0.x, a0.y, a0.z, a0.w, a1.x, a1.y, a1.z, a1.w};
            float rb[8] = {b0.x, b0.y, b0.z, b0.w, b1.x, b1.y, b1.z, b1.w};
#pragma unroll
            for (int m = 0; m < 8; m++)
#pragma unroll
                for (int n = 0; n < 8; n++)
                    acc[m][n] += fminf(ra[m], rb[n]);
        }
        __syncthreads();
    }

    // ---- epilogue: out = max(rsA + rsB - 2*accmin, 0), stored as float4 ----
    float rsa[8], rsb[8];
#pragma unroll
    for (int m = 0; m < 8; m++)
        rsa[m] = rsAs[ty * 4 + (m & 3) + ((m >> 2) << 6)];
#pragma unroll
    for (int n = 0; n < 8; n++)
        rsb[n] = rsBs[tx * 4 + (n & 3) + ((n >> 2) << 6)];

#pragma unroll
    for (int m = 0; m < 8; m++) {
        int r = i0 + ty * 4 + (m & 3) + ((m >> 2) << 6);
        float* orow = out + (size_t)r * N2 + j0 + tx * 4;
#pragma unroll
        for (int n4 = 0; n4 < 2; n4++) {
            float v0 = fmaxf(fmaf(-2.f, acc[m][n4 * 4 + 0], rsa[m] + rsb[n4 * 4 + 0]), 0.f);
            float v1 = fmaxf(fmaf(-2.f, acc[m][n4 * 4 + 1], rsa[m] + rsb[n4 * 4 + 1]), 0.f);
            float v2 = fmaxf(fmaf(-2.f, acc[m][n4 * 4 + 2], rsa[m] + rsb[n4 * 4 + 2]), 0.f);
            float v3 = fmaxf(fmaf(-2.f, acc[m][n4 * 4 + 3], rsa[m] + rsb[n4 * 4 + 3]), 0.f);
            *(float4*)(orow + (n4 << 6)) = make_float4(v0, v1, v2, v3);
        }
    }
}

extern "C" void kernel_launch(void* const* d_in, const int* in_sizes, int n_in,
                              void* d_out, int out_size) {
    const float* x1 = (const float*)d_in[0];
    const float* x2 = (const float*)d_in[1];
    float* out = (float*)d_out;

    int N1 = in_sizes[0] / D;   // 2048
    int N2 = in_sizes[1] / D;   // 2048

    rowsum_kernel<<<(N1 + 255) / 256, 256>>>(x1, x2, N1);

    dim3 grid(N2 / TILE, N1 / TILE);   // 16 x 16
    l1dist_kernel<<<grid, 256>>>(x1, x2, out, N2);
}

// round 4
// speedup vs baseline: 1.1332x; 1.1301x over previous
#include <cuda_runtime.h>

// L1Distance via the min identity:
//   out[i][j] = max(rowsumA[i] + rowsumB[j] - 2 * sum_d min(x1[i,d], x2[j,d]), 0)
// (mean adjustment cancels exactly). Inner op = 1 FMNMX (alu) + 1 FADD (fma)
// per pair -> 2 issue slots/pair, pipes balanced. This round: occupancy up
// (64x128 tiles, ~32 acc regs, 3 CTAs/SM) + properly parallel rowsum kernel.

constexpr int D      = 64;
constexpr int TM     = 64;    // tile rows  (i)
constexpr int TN     = 128;   // tile cols  (j)
constexpr int DCHUNK = 32;
constexpr int SA     = 68;    // As stride (64 + 4 pad)
constexpr int SB     = 132;   // Bs stride (128 + 4 pad)

__device__ float d_rsA[2048];
__device__ float d_rsB[2048];

// one warp per row; both matrices covered by 4096 warps
__global__ void rowsum_kernel(const float* __restrict__ x1,
                              const float* __restrict__ x2, int N) {
    int w    = (blockIdx.x * blockDim.x + threadIdx.x) >> 5;  // global warp id
    int lane = threadIdx.x & 31;
    if (w >= 2 * N) return;
    const float* src = (w < N) ? x1 : x2;
    int row = (w < N) ? w : w - N;
    float s = src[(size_t)row * D + lane] + src[(size_t)row * D + lane + 32];
#pragma unroll
    for (int off = 16; off > 0; off >>= 1)
        s += __shfl_xor_sync(0xffffffffu, s, off);
    if (lane == 0) {
        if (w < N) d_rsA[row] = s;
        else       d_rsB[row] = s;
    }
}

__global__ __launch_bounds__(256, 3)
void l1dist_kernel(const float* __restrict__ x1, const float* __restrict__ x2,
                   float* __restrict__ out, int N2) {
    __shared__ __align__(16) float As[DCHUNK * SA];  // As[d][row] = x1[i0+row][dc+d]
    __shared__ __align__(16) float Bs[DCHUNK * SB];  // Bs[d][row] = x2[j0+row][dc+d]
    __shared__ float rsAs[TM];
    __shared__ float rsBs[TN];

    const int i0  = blockIdx.y * TM;
    const int j0  = blockIdx.x * TN;
    const int tid = (int)threadIdx.x;
    const int ty  = tid >> 4;   // 0..15 -> 4 rows each
    const int tx  = tid & 15;   // 0..15 -> 4+4 cols each

    if (tid < TM)            rsAs[tid] = d_rsA[i0 + tid];
    else if (tid < TM + TN)  rsBs[tid - TM] = d_rsB[j0 + tid - TM];

    float acc[4][8];
#pragma unroll
    for (int m = 0; m < 4; m++)
#pragma unroll
        for (int n = 0; n < 8; n++) acc[m][n] = 0.0f;

    for (int dc = 0; dc < D; dc += DCHUNK) {
        // ---- stage A: 64 rows x 32 d = 512 float4, 2 per thread ----
#pragma unroll
        for (int k = 0; k < 2; k++) {
            int idx = tid + k * 256;        // 0..511
            int row = idx >> 3;             // 0..63
            int d4  = (idx & 7) << 2;       // 0,4,...,28
            float4 a = *(const float4*)(x1 + (size_t)(i0 + row) * D + dc + d4);
            As[(d4 + 0) * SA + row] = a.x;
            As[(d4 + 1) * SA + row] = a.y;
            As[(d4 + 2) * SA + row] = a.z;
            As[(d4 + 3) * SA + row] = a.w;
        }
        // ---- stage B: 128 rows x 32 d = 1024 float4, 4 per thread ----
#pragma unroll
        for (int k = 0; k < 4; k++) {
            int idx = tid + k * 256;        // 0..1023
            int row = idx >> 3;             // 0..127
            int d4  = (idx & 7) << 2;
            float4 b = *(const float4*)(x2 + (size_t)(j0 + row) * D + dc + d4);
            Bs[(d4 + 0) * SB + row] = b.x;
            Bs[(d4 + 1) * SB + row] = b.y;
            Bs[(d4 + 2) * SB + row] = b.z;
            Bs[(d4 + 3) * SB + row] = b.w;
        }
        __syncthreads();

        // ---- compute: 1 LDS.128 (a) + 2 LDS.128 (b) + 32 FMNMX + 32 FADD per d
#pragma unroll 8
        for (int d = 0; d < DCHUNK; d++) {
            const float* as = &As[d * SA];
            const float* bs = &Bs[d * SB];
            float4 av = *(const float4*)(as + ty * 4);
            float4 b0 = *(const float4*)(bs + tx * 4);
            float4 b1 = *(const float4*)(bs + tx * 4 + 64);
            float ra[4] = {av.x, av.y, av.z, av.w};
            float rb[8] = {b0.x, b0.y, b0.z, b0.w, b1.x, b1.y, b1.z, b1.w};
#pragma unroll
            for (int m = 0; m < 4; m++)
#pragma unroll
                for (int n = 0; n < 8; n++)
                    acc[m][n] += fminf(ra[m], rb[n]);
        }
        __syncthreads();
    }

    // ---- epilogue: out = max(rsA + rsB - 2*accmin, 0) ----
    float rsb[8];
#pragma unroll
    for (int n = 0; n < 8; n++)
        rsb[n] = rsBs[tx * 4 + (n & 3) + ((n >> 2) << 6)];

#pragma unroll
    for (int m = 0; m < 4; m++) {
        float rsa = rsAs[ty * 4 + m];
        int r = i0 + ty * 4 + m;
        float* orow = out + (size_t)r * N2 + j0 + tx * 4;
#pragma unroll
        for (int n4 = 0; n4 < 2; n4++) {
            float v0 = fmaxf(fmaf(-2.f, acc[m][n4 * 4 + 0], rsa + rsb[n4 * 4 + 0]), 0.f);
            float v1 = fmaxf(fmaf(-2.f, acc[m][n4 * 4 + 1], rsa + rsb[n4 * 4 + 1]), 0.f);
            float v2 = fmaxf(fmaf(-2.f, acc[m][n4 * 4 + 2], rsa + rsb[n4 * 4 + 2]), 0.f);
            float v3 = fmaxf(fmaf(-2.f, acc[m][n4 * 4 + 3], rsa + rsb[n4 * 4 + 3]), 0.f);
            *(float4*)(orow + (n4 << 6)) = make_float4(v0, v1, v2, v3);
        }
    }
}

extern "C" void kernel_launch(void* const* d_in, const int* in_sizes, int n_in,
                              void* d_out, int out_size) {
    const float* x1 = (const float*)d_in[0];
    const float* x2 = (const float*)d_in[1];
    float* out = (float*)d_out;

    int N1 = in_sizes[0] / D;   // 2048
    int N2 = in_sizes[1] / D;   // 2048

    // 4096 warps total: one per row of each matrix
    int warps = 2 * N1;
    rowsum_kernel<<<(warps * 32 + 255) / 256, 256>>>(x1, x2, N1);

    dim3 grid(N2 / TN, N1 / TM);   // 16 x 32 = 512 blocks
    l1dist_kernel<<<grid, 256>>>(x1, x2, out, N2);
}

// round 5
// speedup vs baseline: 1.2022x; 1.0609x over previous
#include <cuda_runtime.h>

// L1Distance via the min identity:
//   out[i][j] = max(rowsumA[i] + rowsumB[j] - 2 * sum_d min(x1[i,d], x2[j,d]), 0)
// (mean adjustment cancels exactly). Inner op = 1 FMNMX (alu) + 1 FADD (fma).
// Single kernel: 64x64 tiles, whole D staged once, rowsums computed in-block
// from the staged tiles. 4 CTAs/SM (32 warps) for issue-slot saturation.

constexpr int D    = 64;
constexpr int TM   = 64;
constexpr int TN   = 64;
constexpr int SA   = 68;   // padded stride (floats) for transposed tiles

__global__ __launch_bounds__(256, 4)
void l1dist_kernel(const float* __restrict__ x1, const float* __restrict__ x2,
                   float* __restrict__ out, int N2) {
    __shared__ __align__(16) float As[D * SA];  // As[d][row] = x1[i0+row][d]
    __shared__ __align__(16) float Bs[D * SA];  // Bs[d][row] = x2[j0+row][d]
    __shared__ float rsAs[TM];
    __shared__ float rsBs[TN];

    const int i0  = blockIdx.y * TM;
    const int j0  = blockIdx.x * TN;
    const int tid = (int)threadIdx.x;
    const int ty  = tid >> 4;   // 0..15 -> rows ty*4..ty*4+3
    const int tx  = tid & 15;   // 0..15 -> cols tx*4..tx*4+3

    // ---- stage both tiles, transposed: 64 rows x 64 d = 1024 float4 each ----
#pragma unroll
    for (int k = 0; k < 4; k++) {
        int idx = tid + k * 256;        // 0..1023
        int row = idx >> 4;             // 0..63
        int d4  = (idx & 15) << 2;      // 0,4,...,60
        float4 a = *(const float4*)(x1 + (size_t)(i0 + row) * D + d4);
        As[(d4 + 0) * SA + row] = a.x;
        As[(d4 + 1) * SA + row] = a.y;
        As[(d4 + 2) * SA + row] = a.z;
        As[(d4 + 3) * SA + row] = a.w;
        float4 b = *(const float4*)(x2 + (size_t)(j0 + row) * D + d4);
        Bs[(d4 + 0) * SA + row] = b.x;
        Bs[(d4 + 1) * SA + row] = b.y;
        Bs[(d4 + 2) * SA + row] = b.z;
        Bs[(d4 + 3) * SA + row] = b.w;
    }
    __syncthreads();

    // ---- in-block rowsums from staged tiles (threads 0..127) ----
    if (tid < TM + TN) {
        const float* col = (tid < TM) ? &As[tid] : &Bs[tid - TM];
        float s = 0.f;
#pragma unroll
        for (int d = 0; d < D; d++) s += col[d * SA];
        if (tid < TM) rsAs[tid] = s;
        else          rsBs[tid - TM] = s;
    }

    // ---- main compute: acc[m][n] += min(a_m, b_n) over all 64 d ----
    float acc[4][4];
#pragma unroll
    for (int m = 0; m < 4; m++)
#pragma unroll
        for (int n = 0; n < 4; n++) acc[m][n] = 0.0f;

#pragma unroll 8
    for (int d = 0; d < D; d++) {
        float4 av = *(const float4*)(&As[d * SA] + ty * 4);
        float4 bv = *(const float4*)(&Bs[d * SA] + tx * 4);
        float ra[4] = {av.x, av.y, av.z, av.w};
        float rb[4] = {bv.x, bv.y, bv.z, bv.w};
#pragma unroll
        for (int m = 0; m < 4; m++)
#pragma unroll
            for (int n = 0; n < 4; n++)
                acc[m][n] += fminf(ra[m], rb[n]);
    }
    __syncthreads();   // rowsum writes -> epilogue reads

    // ---- epilogue: out = max(rsA + rsB - 2*accmin, 0) ----
    float rsb[4] = {rsBs[tx * 4 + 0], rsBs[tx * 4 + 1],
                    rsBs[tx * 4 + 2], rsBs[tx * 4 + 3]};
#pragma unroll
    for (int m = 0; m < 4; m++) {
        float rsa = rsAs[ty * 4 + m];
        int r = i0 + ty * 4 + m;
        float* orow = out + (size_t)r * N2 + j0 + tx * 4;
        float v0 = fmaxf(fmaf(-2.f, acc[m][0], rsa + rsb[0]), 0.f);
        float v1 = fmaxf(fmaf(-2.f, acc[m][1], rsa + rsb[1]), 0.f);
        float v2 = fmaxf(fmaf(-2.f, acc[m][2], rsa + rsb[2]), 0.f);
        float v3 = fmaxf(fmaf(-2.f, acc[m][3], rsa + rsb[3]), 0.f);
        *(float4*)orow = make_float4(v0, v1, v2, v3);
    }
}

extern "C" void kernel_launch(void* const* d_in, const int* in_sizes, int n_in,
                              void* d_out, int out_size) {
    const float* x1 = (const float*)d_in[0];
    const float* x2 = (const float*)d_in[1];
    float* out = (float*)d_out;

    int N1 = in_sizes[0] / D;   // 2048
    int N2 = in_sizes[1] / D;   // 2048

    dim3 grid(N2 / TN, N1 / TM);   // 32 x 32 = 1024 blocks
    l1dist_kernel<<<grid, 256>>>(x1, x2, out, N2);
}

// round 6
// speedup vs baseline: 1.2035x; 1.0011x over previous
#include <cuda_runtime.h>

// L1Distance via the min identity:
//   out[i][j] = max(rowsumA[i] + rowsumB[j] - 2 * sum_d min(x1[i,d], x2[j,d]), 0)
// (mean adjustment cancels exactly). Inner op = 1 FMNMX (alu) + 1 FADD (fma).
// This round: 128x64 block tile, 8x4 thread tile (fewer LDS bytes/pair),
// explicit software-pipelined fragment loads to kill LDS long-scoreboard stalls.

constexpr int D   = 64;
constexpr int TM  = 128;   // tile rows (x1)
constexpr int TN  = 64;    // tile cols (x2)
constexpr int DC  = 32;    // d staged in two chunks
constexpr int SAA = 132;   // As stride (128 + 4 pad)
constexpr int SAB = 68;    // Bs stride (64 + 4 pad)

__global__ __launch_bounds__(256, 3)
void l1dist_kernel(const float* __restrict__ x1, const float* __restrict__ x2,
                   float* __restrict__ out, int N2) {
    __shared__ __align__(16) float As[DC * SAA];  // As[d][row] = x1[i0+row][dc+d]
    __shared__ __align__(16) float Bs[DC * SAB];  // Bs[d][row] = x2[j0+row][dc+d]
    __shared__ float rsAs[TM];
    __shared__ float rsBs[TN];

    const int i0  = blockIdx.y * TM;
    const int j0  = blockIdx.x * TN;
    const int tid = (int)threadIdx.x;
    const int ty  = tid >> 4;   // 0..15 -> 8 rows each
    const int tx  = tid & 15;   // 0..15 -> 4 cols each

    float acc[8][4];
#pragma unroll
    for (int m = 0; m < 8; m++)
#pragma unroll
        for (int n = 0; n < 4; n++) acc[m][n] = 0.0f;

    float rs = 0.0f;   // per-thread rowsum (threads 0..191)

    for (int dc = 0; dc < D; dc += DC) {
        // ---- stage A: 128 rows x 32 d = 1024 float4, 4 per thread ----
#pragma unroll
        for (int k = 0; k < 4; k++) {
            int idx = tid + k * 256;        // 0..1023
            int row = idx >> 3;             // 0..127
            int d4  = (idx & 7) << 2;       // 0,4,...,28
            float4 a = *(const float4*)(x1 + (size_t)(i0 + row) * D + dc + d4);
            As[(d4 + 0) * SAA + row] = a.x;
            As[(d4 + 1) * SAA + row] = a.y;
            As[(d4 + 2) * SAA + row] = a.z;
            As[(d4 + 3) * SAA + row] = a.w;
        }
        // ---- stage B: 64 rows x 32 d = 512 float4, 2 per thread ----
#pragma unroll
        for (int k = 0; k < 2; k++) {
            int idx = tid + k * 256;        // 0..511
            int row = idx >> 3;             // 0..63
            int d4  = (idx & 7) << 2;
            float4 b = *(const float4*)(x2 + (size_t)(j0 + row) * D + dc + d4);
            Bs[(d4 + 0) * SAB + row] = b.x;
            Bs[(d4 + 1) * SAB + row] = b.y;
            Bs[(d4 + 2) * SAB + row] = b.z;
            Bs[(d4 + 3) * SAB + row] = b.w;
        }
        __syncthreads();

        // ---- partial rowsums from staged tiles (warps 0..5) ----
        if (tid < TM) {
            const float* col = &As[tid];
#pragma unroll
            for (int d = 0; d < DC; d++) rs += col[d * SAA];
        } else if (tid < TM + TN) {
            const float* col = &Bs[tid - TM];
#pragma unroll
            for (int d = 0; d < DC; d++) rs += col[d * SAB];
        }

        // ---- software-pipelined compute over the chunk ----
        float4 a0 = *(const float4*)(&As[0] + ty * 8);
        float4 a1 = *(const float4*)(&As[0] + ty * 8 + 4);
        float4 b0 = *(const float4*)(&Bs[0] + tx * 4);
#pragma unroll 8
        for (int d = 0; d < DC; d++) {
            int dn = (d + 1) & (DC - 1);   // wrap: last iter reloads d=0 (harmless)
            float4 na0 = *(const float4*)(&As[dn * SAA] + ty * 8);
            float4 na1 = *(const float4*)(&As[dn * SAA] + ty * 8 + 4);
            float4 nb0 = *(const float4*)(&Bs[dn * SAB] + tx * 4);

            float ra[8] = {a0.x, a0.y, a0.z, a0.w, a1.x, a1.y, a1.z, a1.w};
            float rb[4] = {b0.x, b0.y, b0.z, b0.w};
#pragma unroll
            for (int m = 0; m < 8; m++)
#pragma unroll
                for (int n = 0; n < 4; n++)
                    acc[m][n] += fminf(ra[m], rb[n]);

            a0 = na0; a1 = na1; b0 = nb0;
        }
        __syncthreads();
    }

    // ---- publish rowsums, then epilogue ----
    if (tid < TM)            rsAs[tid] = rs;
    else if (tid < TM + TN)  rsBs[tid - TM] = rs;
    __syncthreads();

    float rsb[4] = {rsBs[tx * 4 + 0], rsBs[tx * 4 + 1],
                    rsBs[tx * 4 + 2], rsBs[tx * 4 + 3]};
#pragma unroll
    for (int m = 0; m < 8; m++) {
        float rsa = rsAs[ty * 8 + m];
        int r = i0 + ty * 8 + m;
        float* orow = out + (size_t)r * N2 + j0 + tx * 4;
        float v0 = fmaxf(fmaf(-2.f, acc[m][0], rsa + rsb[0]), 0.f);
        float v1 = fmaxf(fmaf(-2.f, acc[m][1], rsa + rsb[1]), 0.f);
        float v2 = fmaxf(fmaf(-2.f, acc[m][2], rsa + rsb[2]), 0.f);
        float v3 = fmaxf(fmaf(-2.f, acc[m][3], rsa + rsb[3]), 0.f);
        *(float4*)orow = make_float4(v0, v1, v2, v3);
    }
}

extern "C" void kernel_launch(void* const* d_in, const int* in_sizes, int n_in,
                              void* d_out, int out_size) {
    const float* x1 = (const float*)d_in[0];
    const float* x2 = (const float*)d_in[1];
    float* out = (float*)d_out;

    int N1 = in_sizes[0] / D;   // 2048
    int N2 = in_sizes[1] / D;   // 2048

    dim3 grid(N2 / TN, N1 / TM);   // 32 x 16 = 512 blocks
    l1dist_kernel<<<grid, 256>>>(x1, x2, out, N2);
}

// round 7
// speedup vs baseline: 1.2141x; 1.0088x over previous
#include <cuda_runtime.h>

// L1Distance via the min identity:
//   out[i][j] = max(rowsumA[i] + rowsumB[j] - 2 * sum_d min(x1[i,d], x2[j,d]), 0)
// (mean adjustment cancels exactly; clamp is a no-op but kept).
// Inner math: scalar FMNMX (alu pipe) + packed add.rn.f32x2 accumulate
// (fma pipe) -> 1.5 math instrs per element-pair instead of 2.

constexpr int D   = 64;
constexpr int TM  = 128;   // tile rows (x1)
constexpr int TN  = 64;    // tile cols (x2)
constexpr int DC  = 32;    // d staged in two chunks
constexpr int SAA = 132;   // As stride (128 + 4 pad)
constexpr int SAB = 68;    // Bs stride (64 + 4 pad)

__device__ __forceinline__ void acc2(unsigned long long& acc, float lo, float hi) {
    unsigned long long t;
    asm("mov.b64 %0, {%1, %2};" : "=l"(t) : "f"(lo), "f"(hi));
    asm("add.rn.f32x2 %0, %0, %1;" : "+l"(acc) : "l"(t));
}

__global__ __launch_bounds__(256, 3)
void l1dist_kernel(const float* __restrict__ x1, const float* __restrict__ x2,
                   float* __restrict__ out, int N2) {
    __shared__ __align__(16) float As[DC * SAA];  // As[d][row] = x1[i0+row][dc+d]
    __shared__ __align__(16) float Bs[DC * SAB];  // Bs[d][row] = x2[j0+row][dc+d]
    __shared__ float rsAs[TM];
    __shared__ float rsBs[TN];

    const int i0  = blockIdx.y * TM;
    const int j0  = blockIdx.x * TN;
    const int tid = (int)threadIdx.x;
    const int ty  = tid >> 4;   // 0..15 -> 8 rows each
    const int tx  = tid & 15;   // 0..15 -> 4 cols each

    // acc[m][p] packs mins for cols (tx*4+2p, tx*4+2p+1), rows ty*8+m
    unsigned long long acc[8][2];
#pragma unroll
    for (int m = 0; m < 8; m++) { acc[m][0] = 0ULL; acc[m][1] = 0ULL; }

    float rs = 0.0f;   // per-thread rowsum piece (threads 0..191)

    for (int dc = 0; dc < D; dc += DC) {
        // ---- stage A: 128 rows x 32 d = 1024 float4, 4 per thread ----
#pragma unroll
        for (int k = 0; k < 4; k++) {
            int idx = tid + k * 256;
            int row = idx >> 3;             // 0..127
            int d4  = (idx & 7) << 2;       // 0,4,...,28
            float4 a = *(const float4*)(x1 + (size_t)(i0 + row) * D + dc + d4);
            As[(d4 + 0) * SAA + row] = a.x;
            As[(d4 + 1) * SAA + row] = a.y;
            As[(d4 + 2) * SAA + row] = a.z;
            As[(d4 + 3) * SAA + row] = a.w;
        }
        // ---- stage B: 64 rows x 32 d = 512 float4, 2 per thread ----
#pragma unroll
        for (int k = 0; k < 2; k++) {
            int idx = tid + k * 256;
            int row = idx >> 3;             // 0..63
            int d4  = (idx & 7) << 2;
            float4 b = *(const float4*)(x2 + (size_t)(j0 + row) * D + dc + d4);
            Bs[(d4 + 0) * SAB + row] = b.x;
            Bs[(d4 + 1) * SAB + row] = b.y;
            Bs[(d4 + 2) * SAB + row] = b.z;
            Bs[(d4 + 3) * SAB + row] = b.w;
        }
        __syncthreads();

        // ---- partial rowsums from staged tiles (warps 0..5) ----
        if (tid < TM) {
            const float* col = &As[tid];
#pragma unroll
            for (int d = 0; d < DC; d++) rs += col[d * SAA];
        } else if (tid < TM + TN) {
            const float* col = &Bs[tid - TM];
#pragma unroll
            for (int d = 0; d < DC; d++) rs += col[d * SAB];
        }

        // ---- compute: per d, 32 FMNMX (alu) + 16 FADD2 (fma) + 3 LDS.128 ----
#pragma unroll 8
        for (int d = 0; d < DC; d++) {
            float4 a0 = *(const float4*)(&As[d * SAA] + ty * 8);
            float4 a1 = *(const float4*)(&As[d * SAA] + ty * 8 + 4);
            float4 bv = *(const float4*)(&Bs[d * SAB] + tx * 4);
            float ra[8] = {a0.x, a0.y, a0.z, a0.w, a1.x, a1.y, a1.z, a1.w};
#pragma unroll
            for (int m = 0; m < 8; m++) {
                acc2(acc[m][0], fminf(ra[m], bv.x), fminf(ra[m], bv.y));
                acc2(acc[m][1], fminf(ra[m], bv.z), fminf(ra[m], bv.w));
            }
        }
        __syncthreads();
    }

    // ---- publish rowsums, then epilogue ----
    if (tid < TM)            rsAs[tid] = rs;
    else if (tid < TM + TN)  rsBs[tid - TM] = rs;
    __syncthreads();

    float rsb[4] = {rsBs[tx * 4 + 0], rsBs[tx * 4 + 1],
                    rsBs[tx * 4 + 2], rsBs[tx * 4 + 3]};
#pragma unroll
    for (int m = 0; m < 8; m++) {
        float rsa = rsAs[ty * 8 + m];
        int r = i0 + ty * 8 + m;
        float* orow = out + (size_t)r * N2 + j0 + tx * 4;
        float2 p0 = *(float2*)&acc[m][0];
        float2 p1 = *(float2*)&acc[m][1];
        float v0 = fmaxf(fmaf(-2.f, p0.x, rsa + rsb[0]), 0.f);
        float v1 = fmaxf(fmaf(-2.f, p0.y, rsa + rsb[1]), 0.f);
        float v2 = fmaxf(fmaf(-2.f, p1.x, rsa + rsb[2]), 0.f);
        float v3 = fmaxf(fmaf(-2.f, p1.y, rsa + rsb[3]), 0.f);
        *(float4*)orow = make_float4(v0, v1, v2, v3);
    }
}

extern "C" void kernel_launch(void* const* d_in, const int* in_sizes, int n_in,
                              void* d_out, int out_size) {
    const float* x1 = (const float*)d_in[0];
    const float* x2 = (const float*)d_in[1];
    float* out = (float*)d_out;

    int N1 = in_sizes[0] / D;   // 2048
    int N2 = in_sizes[1] / D;   // 2048

    dim3 grid(N2 / TN, N1 / TM);   // 32 x 16 = 512 blocks
    l1dist_kernel<<<grid, 256>>>(x1, x2, out, N2);
}